// round 1
// baseline (speedup 1.0000x reference)
#include <cuda_runtime.h>
#include <cstdint>

#define BATCH 4
#define NPTS  8192
#define HH    2048
#define WW    2048
#define KOUT  1024
#define RAD   4

// Persistent scratch (zero-initialized at module load; every launch restores
// the grid to all-zero at the end, so graph replays are deterministic).
__device__ __align__(16) unsigned int g_grid[BATCH * HH * WW]; // 64 MB, float bits
__device__ unsigned int g_pix[BATCH * NPTS];
__device__ float        g_masked[BATCH * NPTS];

// ---------------------------------------------------------------------------
// K1: scatter-max score bits into the per-batch grid; cache pixel ids.
// Positive floats compare identically as unsigned ints, and the grid's zero
// init is 0.0f, matching jnp.zeros().at[y,x].max(scores).
// ---------------------------------------------------------------------------
__global__ void scatter_kernel(const float* __restrict__ lafs,
                               const float* __restrict__ scores) {
    int i = blockIdx.x * blockDim.x + threadIdx.x;
    if (i >= BATCH * NPTS) return;
    float x = lafs[i * 6 + 2];   // laf[:,0,2] = x
    float y = lafs[i * 6 + 5];   // laf[:,1,2] = y
    int xi = (int)rintf(x); xi = min(max(xi, 0), WW - 1);  // rintf == jnp.round (RNE)
    int yi = (int)rintf(y); yi = min(max(yi, 0), HH - 1);
    unsigned p = ((unsigned)(i >> 13) << 22) | ((unsigned)yi << 11) | (unsigned)xi;
    g_pix[i] = p;
    atomicMax(&g_grid[p], __float_as_uint(scores[i]));
}

// ---------------------------------------------------------------------------
// K2: per-keypoint 9x9 windowed max read directly from the sparse grid.
// survive = (score == grid[y,x]) && (windowmax == grid[y,x])
// Rows are read as aligned float4 chunks (<=3 per row) with per-element
// column masking; values are >= 0 so wmax starts at 0.
// ---------------------------------------------------------------------------
__global__ void nms_kernel(const float* __restrict__ scores) {
    int i = blockIdx.x * blockDim.x + threadIdx.x;
    if (i >= BATCH * NPTS) return;
    unsigned p = g_pix[i];
    int xi = p & (WW - 1);
    int yi = (p >> 11) & (HH - 1);
    const float* gb = reinterpret_cast<const float*>(g_grid) + (p & 0xFFC00000u);

    float v = __uint_as_float(g_grid[p]);
    float s = scores[i];

    int y0 = max(yi - RAD, 0), y1 = min(yi + RAD, HH - 1);
    int x0 = max(xi - RAD, 0), x1 = min(xi + RAD, WW - 1);
    int q0 = x0 >> 2, q1 = x1 >> 2;

    float wmax = 0.0f;
    for (int yy = y0; yy <= y1; ++yy) {
        const float4* row = reinterpret_cast<const float4*>(gb + yy * WW);
        for (int q = q0; q <= q1; ++q) {
            float4 d = row[q];
            int c = q << 2;
            if (c     >= x0 && c     <= x1) wmax = fmaxf(wmax, d.x);
            if (c + 1 >= x0 && c + 1 <= x1) wmax = fmaxf(wmax, d.y);
            if (c + 2 >= x0 && c + 2 <= x1) wmax = fmaxf(wmax, d.z);
            if (c + 3 >= x0 && c + 3 <= x1) wmax = fmaxf(wmax, d.w);
        }
    }
    bool survive = (s == v) && (wmax <= v);   // wmax >= v always (window holds center)
    g_masked[i] = survive ? s : __int_as_float(0xFF800000);  // -inf
}

// ---------------------------------------------------------------------------
// K3: per-batch block: (a) restore the grid to zero for the touched pixels,
// (b) bitonic sort 8192 64-bit keys (score-mapped desc, index asc tie-break,
// exactly matching lax.top_k), (c) write top-1024 lafs + scores.
// ---------------------------------------------------------------------------
__global__ void topk_kernel(const float* __restrict__ lafs,
                            float* __restrict__ out) {
    extern __shared__ unsigned long long keybuf[];  // 8192 * 8B = 64 KB
    int b   = blockIdx.x;
    int tid = threadIdx.x;

    // (a) cleanup: restore persistent grid to all-zero for determinism
    for (int i = tid; i < NPTS; i += blockDim.x)
        g_grid[g_pix[b * NPTS + i]] = 0u;

    // (b) build sortable keys: monotone float->uint map, ~idx tie-break
    for (int i = tid; i < NPTS; i += blockDim.x) {
        unsigned sb = __float_as_uint(g_masked[b * NPTS + i]);
        unsigned m  = (sb & 0x80000000u) ? ~sb : (sb | 0x80000000u);
        keybuf[i] = ((unsigned long long)m << 32) | (unsigned)(~i);
    }
    __syncthreads();

    // full bitonic sort, descending
    for (int k = 2; k <= NPTS; k <<= 1) {
        for (int j = k >> 1; j > 0; j >>= 1) {
            for (int t = tid; t < NPTS; t += blockDim.x) {
                int l = t ^ j;
                if (l > t) {
                    unsigned long long a = keybuf[t];
                    unsigned long long c = keybuf[l];
                    bool up = (t & k) == 0;
                    if (up ? (a < c) : (a > c)) { keybuf[t] = c; keybuf[l] = a; }
                }
            }
            __syncthreads();
        }
    }

    // (c) outputs: lafs_out [4,1024,2,3] then scores_out [4,1024]
    {
        unsigned long long kk = keybuf[tid];
        int idx = (int)((~(unsigned)kk) & (NPTS - 1));
        unsigned m  = (unsigned)(kk >> 32);
        unsigned sb = (m & 0x80000000u) ? (m & 0x7FFFFFFFu) : ~m;
        float sc = __uint_as_float(sb);

        const float2* src = reinterpret_cast<const float2*>(lafs + (size_t)(b * NPTS + idx) * 6);
        float2*       dst = reinterpret_cast<float2*>(out + (size_t)(b * KOUT + tid) * 6);
        dst[0] = src[0];
        dst[1] = src[1];
        dst[2] = src[2];
        out[BATCH * KOUT * 6 + b * KOUT + tid] = sc;
    }
}

extern "C" void kernel_launch(void* const* d_in, const int* in_sizes, int n_in,
                              void* d_out, int out_size) {
    const float* lafs   = (const float*)d_in[0];
    const float* scores = (const float*)d_in[1];
    float* out = (float*)d_out;

    // opt-in to 64 KB dynamic smem for the sort kernel (idempotent, non-stream API)
    cudaFuncSetAttribute(topk_kernel, cudaFuncAttributeMaxDynamicSharedMemorySize, 65536);

    int nthr = BATCH * NPTS;
    scatter_kernel<<<(nthr + 255) / 256, 256>>>(lafs, scores);
    nms_kernel<<<(nthr + 255) / 256, 256>>>(scores);
    topk_kernel<<<BATCH, 1024, 65536>>>(lafs, out);
}

// round 2
// speedup vs baseline: 3.6109x; 3.6109x over previous
#include <cuda_runtime.h>
#include <cstdint>

#define BATCH 4
#define NPTS  8192
#define HH    2048
#define WW    2048
#define KOUT  1024
#define RAD   4

typedef unsigned long long ull;

// Persistent scratch (zero-init at module load; every launch restores the grid
// to all-zero before finishing, so graph replays are deterministic).
__device__ __align__(16) unsigned int g_grid[BATCH * HH * WW]; // 64 MB, float bits
__device__ unsigned int g_pix[BATCH * NPTS];
__device__ ull          g_keys[BATCH * NPTS];

// ---------------------------------------------------------------------------
// K1: scatter-max score bits into the per-batch grid; cache pixel ids.
// Positive floats compare identically as unsigned; grid zero-init == 0.0f,
// matching jnp.zeros().at[y,x].max(scores).
// ---------------------------------------------------------------------------
__global__ void scatter_kernel(const float* __restrict__ lafs,
                               const float* __restrict__ scores) {
    int i = blockIdx.x * blockDim.x + threadIdx.x;
    if (i >= BATCH * NPTS) return;
    float x = lafs[i * 6 + 2];   // laf[:,0,2] = x
    float y = lafs[i * 6 + 5];   // laf[:,1,2] = y
    int xi = (int)rintf(x); xi = min(max(xi, 0), WW - 1);  // rintf == jnp.round (RNE)
    int yi = (int)rintf(y); yi = min(max(yi, 0), HH - 1);
    unsigned p = ((unsigned)(i >> 13) << 22) | ((unsigned)yi << 11) | (unsigned)xi;
    g_pix[i] = p;
    atomicMax(&g_grid[p], __float_as_uint(scores[i]));
}

// ---------------------------------------------------------------------------
// K2: per-keypoint 9x9 windowed max read directly from the sparse grid, then
// emit the 64-bit sort key: (monotone score map << 32) | ~idx.
// survive = (score == grid[y,x]) && (windowmax == grid[y,x])
// ---------------------------------------------------------------------------
__global__ void nms_kernel(const float* __restrict__ scores) {
    int i = blockIdx.x * blockDim.x + threadIdx.x;
    if (i >= BATCH * NPTS) return;
    unsigned p = g_pix[i];
    int xi = p & (WW - 1);
    int yi = (p >> 11) & (HH - 1);
    const float* gb = reinterpret_cast<const float*>(g_grid) + (p & 0xFFC00000u);

    float v = __uint_as_float(g_grid[p]);
    float s = scores[i];

    int y0 = max(yi - RAD, 0), y1 = min(yi + RAD, HH - 1);
    int x0 = max(xi - RAD, 0), x1 = min(xi + RAD, WW - 1);
    int q0 = x0 >> 2, q1 = x1 >> 2;

    float wmax = 0.0f;
    for (int yy = y0; yy <= y1; ++yy) {
        const float4* row = reinterpret_cast<const float4*>(gb + yy * WW);
        for (int q = q0; q <= q1; ++q) {
            float4 d = row[q];
            int c = q << 2;
            if (c     >= x0 && c     <= x1) wmax = fmaxf(wmax, d.x);
            if (c + 1 >= x0 && c + 1 <= x1) wmax = fmaxf(wmax, d.y);
            if (c + 2 >= x0 && c + 2 <= x1) wmax = fmaxf(wmax, d.z);
            if (c + 3 >= x0 && c + 3 <= x1) wmax = fmaxf(wmax, d.w);
        }
    }
    bool survive = (s == v) && (wmax <= v);   // wmax >= v always (window holds center)
    unsigned sb = survive ? __float_as_uint(s) : 0xFF800000u;   // -inf if culled
    unsigned m  = (sb & 0x80000000u) ? ~sb : (sb | 0x80000000u);
    g_keys[i] = ((ull)m << 32) | (unsigned)(~i);
}

// ---------------------------------------------------------------------------
// K3: 32 blocks (8 chunks x 4 batches), 512 threads each. Sort each 1024-key
// chunk descending in smem (bitonic, 55 stages, 1 CE/thread/stage) and write
// back in place. Also restores the persistent grid to zero.
// ---------------------------------------------------------------------------
__global__ void __launch_bounds__(512) sort_chunk_kernel() {
    __shared__ ull buf[1024];
    int base = blockIdx.x << 10;       // (b*8 + c) * 1024 == b*NPTS + c*1024
    int tid  = threadIdx.x;

    // cleanup: restore persistent grid (scattered, 32-way parallel)
    g_grid[g_pix[base + tid]]       = 0u;
    g_grid[g_pix[base + tid + 512]] = 0u;

    buf[tid]       = g_keys[base + tid];
    buf[tid + 512] = g_keys[base + tid + 512];
    __syncthreads();

    #pragma unroll 1
    for (int k = 2; k <= 1024; k <<= 1) {
        #pragma unroll 1
        for (int j = k >> 1; j > 0; j >>= 1) {
            int idx = ((tid & ~(j - 1)) << 1) | (tid & (j - 1));
            bool desc = (idx & k) == 0;
            ull x = buf[idx], y = buf[idx | j];
            if ((x < y) == desc) { buf[idx] = y; buf[idx | j] = x; }
            __syncthreads();
        }
    }
    g_keys[base + tid]       = buf[tid];
    g_keys[base + tid + 512] = buf[tid + 512];
}

// ---------------------------------------------------------------------------
// K4: one block per batch. Tree top-k merge of 8 sorted chunks:
// combine(A,B)[i] = max(A[i], B[1023-i]) is the exact top-1024 multiset and is
// bitonic -> 10-stage bitonic merge re-sorts it. 3 levels. Then write outputs.
// ---------------------------------------------------------------------------
__global__ void __launch_bounds__(1024) merge_topk_kernel(const float* __restrict__ lafs,
                                                          float* __restrict__ out) {
    extern __shared__ ull sm[];            // A[4096] ++ B[2048] = 48 KB
    ull* A = sm;
    ull* Bb = sm + 4096;
    int b = blockIdx.x, tid = threadIdx.x;
    const ull* src = g_keys + b * NPTS;

    // level 1: 4 pairwise combines (chunks 2p, 2p+1)
    #pragma unroll
    for (int t = tid; t < 4096; t += 1024) {
        int p = t >> 10, i = t & 1023;
        ull a = src[(p << 11) + i];
        ull c = src[(p << 11) + 1024 + (1023 - i)];
        A[t] = (a > c) ? a : c;
    }
    __syncthreads();
    #pragma unroll 1
    for (int j = 512; j > 0; j >>= 1) {          // merge 4 lists at once
        #pragma unroll
        for (int t = tid; t < 2048; t += 1024) {
            int u = t & 511;
            ull* L = A + ((t >> 9) << 10);
            int idx = ((u & ~(j - 1)) << 1) | (u & (j - 1));
            ull x = L[idx], y = L[idx | j];
            if (x < y) { L[idx] = y; L[idx | j] = x; }
        }
        __syncthreads();
    }

    // level 2: 2 combines -> Bb
    if (tid < 2048) { /* all threads; loop form */ }
    #pragma unroll
    for (int t = tid; t < 2048; t += 1024) {
        int p = t >> 10, i = t & 1023;
        ull a = A[(p << 11) + i];
        ull c = A[(p << 11) + 1024 + (1023 - i)];
        Bb[t] = (a > c) ? a : c;
    }
    __syncthreads();
    #pragma unroll 1
    for (int j = 512; j > 0; j >>= 1) {          // merge 2 lists at once
        int u = tid & 511;
        ull* L = Bb + ((tid >> 9) << 10);
        int idx = ((u & ~(j - 1)) << 1) | (u & (j - 1));
        ull x = L[idx], y = L[idx | j];
        if (x < y) { L[idx] = y; L[idx | j] = x; }
        __syncthreads();
    }

    // level 3: final combine -> A[0..1023]
    {
        ull a = Bb[tid < 1024 ? tid : 0];
        ull c = Bb[1024 + (1023 - (tid < 1024 ? tid : 0))];
        A[tid] = (a > c) ? a : c;
    }
    __syncthreads();
    #pragma unroll 1
    for (int j = 512; j > 0; j >>= 1) {
        if (tid < 512) {
            int idx = ((tid & ~(j - 1)) << 1) | (tid & (j - 1));
            ull x = A[idx], y = A[idx | j];
            if (x < y) { A[idx] = y; A[idx | j] = x; }
        }
        __syncthreads();
    }

    // epilogue: lafs_out [4,1024,2,3] then scores_out [4,1024]
    {
        ull kk = A[tid];
        int idx = (int)((~(unsigned)kk) & (NPTS - 1));
        unsigned m  = (unsigned)(kk >> 32);
        unsigned sb = (m & 0x80000000u) ? (m & 0x7FFFFFFFu) : ~m;
        float sc = __uint_as_float(sb);

        const float2* srcL = reinterpret_cast<const float2*>(lafs + (size_t)(b * NPTS + idx) * 6);
        float2*       dst  = reinterpret_cast<float2*>(out + (size_t)(b * KOUT + tid) * 6);
        dst[0] = srcL[0];
        dst[1] = srcL[1];
        dst[2] = srcL[2];
        out[BATCH * KOUT * 6 + b * KOUT + tid] = sc;
    }
}

extern "C" void kernel_launch(void* const* d_in, const int* in_sizes, int n_in,
                              void* d_out, int out_size) {
    const float* lafs   = (const float*)d_in[0];
    const float* scores = (const float*)d_in[1];
    float* out = (float*)d_out;

    cudaFuncSetAttribute(merge_topk_kernel, cudaFuncAttributeMaxDynamicSharedMemorySize, 49152);

    int nthr = BATCH * NPTS;
    scatter_kernel<<<(nthr + 255) / 256, 256>>>(lafs, scores);
    nms_kernel<<<(nthr + 255) / 256, 256>>>(scores);
    sort_chunk_kernel<<<BATCH * 8, 512>>>();
    merge_topk_kernel<<<BATCH, 1024, 49152>>>(lafs, out);
}

// round 3
// speedup vs baseline: 4.1551x; 1.1507x over previous
#include <cuda_runtime.h>
#include <cstdint>

#define BATCH 4
#define NPTS  8192
#define HH    2048
#define WW    2048
#define KOUT  1024
#define RAD   4

typedef unsigned long long ull;

// Persistent scratch (zero-init at load; every launch restores the grid to
// all-zero before finishing, so graph replays are deterministic).
__device__ __align__(16) unsigned int g_grid[BATCH * HH * WW]; // 64 MB, float bits
__device__ unsigned int g_pix[BATCH * NPTS];
__device__ ull          g_keys[BATCH * NPTS];
__device__ ull          g_keys2[BATCH * 4096];

// Compare-exchange keep: distinct keys guaranteed (low 32 bits = ~idx).
__device__ __forceinline__ ull ce_keep(ull key, ull p, bool keepMax) {
    return (keepMax == (p > key)) ? p : key;
}

// ---------------------------------------------------------------------------
// K1: scatter-max score bits into the per-batch grid; cache pixel ids.
// ---------------------------------------------------------------------------
__global__ void scatter_kernel(const float* __restrict__ lafs,
                               const float* __restrict__ scores) {
    int i = blockIdx.x * blockDim.x + threadIdx.x;
    if (i >= BATCH * NPTS) return;
    const float2* lp = reinterpret_cast<const float2*>(lafs);
    float x = lp[3 * i + 1].x;   // laf[:,0,2]
    float y = lp[3 * i + 2].y;   // laf[:,1,2]
    int xi = (int)rintf(x); xi = min(max(xi, 0), WW - 1);  // rintf == jnp.round (RNE)
    int yi = (int)rintf(y); yi = min(max(yi, 0), HH - 1);
    unsigned p = ((unsigned)(i >> 13) << 22) | ((unsigned)yi << 11) | (unsigned)xi;
    g_pix[i] = p;
    atomicMax(&g_grid[p], __float_as_uint(scores[i]));
}

// ---------------------------------------------------------------------------
// K2: 9x9 windowed max read from the sparse grid; emit 64-bit sort key.
// ---------------------------------------------------------------------------
__global__ void nms_kernel(const float* __restrict__ scores) {
    int i = blockIdx.x * blockDim.x + threadIdx.x;
    if (i >= BATCH * NPTS) return;
    unsigned p = g_pix[i];
    int xi = p & (WW - 1);
    int yi = (p >> 11) & (HH - 1);
    const float* gb = reinterpret_cast<const float*>(g_grid) + (p & 0xFFC00000u);

    float v = __uint_as_float(g_grid[p]);
    float s = scores[i];

    int y0 = max(yi - RAD, 0), y1 = min(yi + RAD, HH - 1);
    int x0 = max(xi - RAD, 0), x1 = min(xi + RAD, WW - 1);
    int q0 = x0 >> 2, q1 = x1 >> 2;

    float wmax = 0.0f;
    for (int yy = y0; yy <= y1; ++yy) {
        const float4* row = reinterpret_cast<const float4*>(gb + yy * WW);
        for (int q = q0; q <= q1; ++q) {
            float4 d = row[q];
            int c = q << 2;
            if (c     >= x0 && c     <= x1) wmax = fmaxf(wmax, d.x);
            if (c + 1 >= x0 && c + 1 <= x1) wmax = fmaxf(wmax, d.y);
            if (c + 2 >= x0 && c + 2 <= x1) wmax = fmaxf(wmax, d.z);
            if (c + 3 >= x0 && c + 3 <= x1) wmax = fmaxf(wmax, d.w);
        }
    }
    bool survive = (s == v) && (wmax <= v);
    unsigned sb = survive ? __float_as_uint(s) : 0xFF800000u;   // -inf if culled
    unsigned m  = (sb & 0x80000000u) ? ~sb : (sb | 0x80000000u);
    g_keys[i] = ((ull)m << 32) | (unsigned)(~i);
}

// ---------------------------------------------------------------------------
// K3: 32 blocks x 1024 thr. Bitonic sort of each 1024-key chunk, descending.
// j<=16 stages via shfl (no barriers); j>=32 via double-buffered smem
// (1 barrier per stage, 15 total). Also restores the grid to zero.
// ---------------------------------------------------------------------------
__global__ void __launch_bounds__(1024) sort_chunk_kernel() {
    __shared__ ull buf[2][1024];
    int t = threadIdx.x;
    int base = blockIdx.x << 10;

    g_grid[g_pix[base + t]] = 0u;       // cleanup (32-way parallel)
    ull key = g_keys[base + t];

    int flip = 0;
    #pragma unroll 1
    for (int k = 2; k <= 1024; k <<= 1) {
        bool desc = (t & k) == 0;       // k=1024 -> all descending
        int j = k >> 1;
        #pragma unroll 1
        for (; j >= 32; j >>= 1) {
            buf[flip][t] = key;
            __syncthreads();
            ull p = buf[flip][t ^ j];
            flip ^= 1;
            key = ce_keep(key, p, desc == ((t & j) == 0));
        }
        #pragma unroll 1
        for (; j >= 1; j >>= 1) {
            ull p = __shfl_xor_sync(0xffffffffu, key, j);
            key = ce_keep(key, p, desc == ((t & j) == 0));
        }
    }
    g_keys[base + t] = key;
}

// ---------------------------------------------------------------------------
// K4: 16 blocks (4 per batch). Combine pair of sorted 1024-lists:
// max(A[i], B[1023-i]) is the exact top-1024 multiset and bitonic ->
// 10-stage merge (5 smem + 5 shfl). Writes sorted lists to g_keys2.
// ---------------------------------------------------------------------------
__global__ void __launch_bounds__(1024) mergeA_kernel() {
    __shared__ ull buf[2][1024];
    int t = threadIdx.x;
    int b = blockIdx.x >> 2, m = blockIdx.x & 3;
    const ull* src = g_keys + (b << 13) + (m << 11);

    ull a = src[t];
    ull c = src[1024 + (1023 - t)];
    ull key = (a > c) ? a : c;

    int flip = 0;
    #pragma unroll 1
    for (int j = 512; j >= 32; j >>= 1) {
        buf[flip][t] = key;
        __syncthreads();
        ull p = buf[flip][t ^ j];
        flip ^= 1;
        key = ce_keep(key, p, (t & j) == 0);
    }
    #pragma unroll
    for (int j = 16; j >= 1; j >>= 1) {
        ull p = __shfl_xor_sync(0xffffffffu, key, j);
        key = ce_keep(key, p, (t & j) == 0);
    }
    g_keys2[b * 4096 + m * 1024 + t] = key;
}

// ---------------------------------------------------------------------------
// K5: 4 blocks (1 per batch). Level 2 (two merges, 2 keys/thread) + level 3
// (final merge) + epilogue: lafs_out [4,1024,2,3] ++ scores_out [4,1024].
// ---------------------------------------------------------------------------
__global__ void __launch_bounds__(1024) mergeBC_kernel(const float* __restrict__ lafs,
                                                       float* __restrict__ out) {
    __shared__ ull buf[2][2048];
    int t = threadIdx.x;
    int b = blockIdx.x;
    const ull* src = g_keys2 + b * 4096;

    // level 2 combine: lists (0,1) -> key0, lists (2,3) -> key1
    ull key0, key1;
    {
        ull a = src[t],        c = src[1024 + (1023 - t)];
        key0 = (a > c) ? a : c;
        ull d = src[2048 + t], e = src[3072 + (1023 - t)];
        key1 = (d > e) ? d : e;
    }
    int flip = 0;
    #pragma unroll 1
    for (int j = 512; j >= 32; j >>= 1) {
        buf[flip][t] = key0;
        buf[flip][1024 + t] = key1;
        __syncthreads();
        ull p0 = buf[flip][t ^ j];
        ull p1 = buf[flip][1024 + (t ^ j)];
        flip ^= 1;
        bool keepMax = (t & j) == 0;
        key0 = ce_keep(key0, p0, keepMax);
        key1 = ce_keep(key1, p1, keepMax);
    }
    #pragma unroll
    for (int j = 16; j >= 1; j >>= 1) {
        ull p0 = __shfl_xor_sync(0xffffffffu, key0, j);
        ull p1 = __shfl_xor_sync(0xffffffffu, key1, j);
        bool keepMax = (t & j) == 0;
        key0 = ce_keep(key0, p0, keepMax);
        key1 = ce_keep(key1, p1, keepMax);
    }

    // level 3 combine
    buf[flip][t] = key0;
    buf[flip][1024 + t] = key1;
    __syncthreads();
    ull key;
    {
        ull a = buf[flip][t];
        ull c = buf[flip][1024 + (1023 - t)];
        key = (a > c) ? a : c;
    }
    flip ^= 1;
    #pragma unroll 1
    for (int j = 512; j >= 32; j >>= 1) {
        buf[flip][t] = key;
        __syncthreads();
        ull p = buf[flip][t ^ j];
        flip ^= 1;
        key = ce_keep(key, p, (t & j) == 0);
    }
    #pragma unroll
    for (int j = 16; j >= 1; j >>= 1) {
        ull p = __shfl_xor_sync(0xffffffffu, key, j);
        key = ce_keep(key, p, (t & j) == 0);
    }

    // epilogue
    {
        int idx = (int)((~(unsigned)key) & (NPTS - 1));
        unsigned m  = (unsigned)(key >> 32);
        unsigned sb = (m & 0x80000000u) ? (m & 0x7FFFFFFFu) : ~m;
        float sc = __uint_as_float(sb);

        const float2* srcL = reinterpret_cast<const float2*>(lafs + (size_t)(b * NPTS + idx) * 6);
        float2*       dst  = reinterpret_cast<float2*>(out + (size_t)(b * KOUT + t) * 6);
        dst[0] = srcL[0];
        dst[1] = srcL[1];
        dst[2] = srcL[2];
        out[BATCH * KOUT * 6 + b * KOUT + t] = sc;
    }
}

extern "C" void kernel_launch(void* const* d_in, const int* in_sizes, int n_in,
                              void* d_out, int out_size) {
    const float* lafs   = (const float*)d_in[0];
    const float* scores = (const float*)d_in[1];
    float* out = (float*)d_out;

    int nthr = BATCH * NPTS;
    scatter_kernel<<<(nthr + 255) / 256, 256>>>(lafs, scores);
    nms_kernel<<<(nthr + 255) / 256, 256>>>(scores);
    sort_chunk_kernel<<<BATCH * 8, 1024>>>();
    mergeA_kernel<<<BATCH * 4, 1024>>>();
    mergeBC_kernel<<<BATCH, 1024>>>(lafs, out);
}